// round 2
// baseline (speedup 1.0000x reference)
#include <cuda_runtime.h>
#include <cuda_bf16.h>

#define NN 50000
#define CC 128
#define EE 640000
#define KK 40
#define LN_EPS 1e-5f

// Scratch (no allocation allowed in kernel_launch)
__device__ float g_deg[NN];
__device__ float g_dinv[NN];
__device__ float g_h[(size_t)NN * CC];
__device__ float g_agg[(size_t)NN * CC];

// ---------------------------------------------------------------- degree ----
__global__ void k_deg_init(int n) {
    int i = blockIdx.x * blockDim.x + threadIdx.x;
    if (i < n) g_deg[i] = 1.0f;  // self-loop
}

__global__ void k_deg_count(const int* __restrict__ dst, int e) {
    int i = blockIdx.x * blockDim.x + threadIdx.x;
    if (i < e) atomicAdd(&g_deg[dst[i]], 1.0f);
}

__global__ void k_dinv(int n) {
    int i = blockIdx.x * blockDim.x + threadIdx.x;
    if (i < n) g_dinv[i] = rsqrtf(g_deg[i]);  // deg >= 1 always
}

// ------------------------------------------------------- h = x @ W_conv ----
// 256 threads/block, 64-row tile, W (128x128) resident in smem.
// Thread t: colgroup cg = t&31 (4 cols), rowgroup rg = t>>5 (8 rows) -> 8x4 microtile.
__global__ void k_gemm_h(const float* __restrict__ x, const float* __restrict__ W, int n) {
    extern __shared__ float sm[];
    float* Ws = sm;               // 128*128 floats (64KB)
    float* Xs = sm + CC * CC;     // 64*128 floats (32KB)
    int t = threadIdx.x;

    float4* Ws4 = (float4*)Ws;
    const float4* W4 = (const float4*)W;
    for (int i = t; i < CC * CC / 4; i += 256) Ws4[i] = W4[i];

    int m0 = blockIdx.x * 64;
    float4* Xs4 = (float4*)Xs;
    for (int i = t; i < 64 * CC / 4; i += 256) {
        int r = i / (CC / 4);
        int cseg = i % (CC / 4);
        float4 v = make_float4(0.f, 0.f, 0.f, 0.f);
        if (m0 + r < n) v = ((const float4*)(x + (size_t)(m0 + r) * CC))[cseg];
        Xs4[i] = v;
    }
    __syncthreads();

    int cg = t & 31;
    int rg = t >> 5;

    float acc[8][4];
#pragma unroll
    for (int r = 0; r < 8; r++)
#pragma unroll
        for (int q = 0; q < 4; q++) acc[r][q] = 0.f;

#pragma unroll 4
    for (int c = 0; c < CC; c++) {
        float4 w = Ws4[c * 32 + cg];
#pragma unroll
        for (int r = 0; r < 8; r++) {
            float xv = Xs[(rg * 8 + r) * CC + c];  // warp-broadcast
            acc[r][0] = fmaf(xv, w.x, acc[r][0]);
            acc[r][1] = fmaf(xv, w.y, acc[r][1]);
            acc[r][2] = fmaf(xv, w.z, acc[r][2]);
            acc[r][3] = fmaf(xv, w.w, acc[r][3]);
        }
    }

#pragma unroll
    for (int r = 0; r < 8; r++) {
        int row = m0 + rg * 8 + r;
        if (row < n) {
            float4 o = make_float4(acc[r][0], acc[r][1], acc[r][2], acc[r][3]);
            ((float4*)(g_h + (size_t)row * CC))[cg] = o;
        }
    }
}

// ------------------------------------------- agg init with self-loop term ----
__global__ void k_agg_init(int n) {
    int idx = blockIdx.x * blockDim.x + threadIdx.x;  // over n * 32 float4s
    if (idx >= n * (CC / 4)) return;
    int node = idx >> 5;
    float s = g_dinv[node];
    s = s * s;  // self-loop norm = dinv^2
    float4 v = ((const float4*)g_h)[idx];
    v.x *= s; v.y *= s; v.z *= s; v.w *= s;
    ((float4*)g_agg)[idx] = v;
}

// ------------------------------------------------------- edge scatter-sum ----
// One warp per edge; lane covers 4 channels; vector REDG.128 atomic.
__global__ void k_scatter(const int* __restrict__ src, const int* __restrict__ dst, int e) {
    int tid = blockIdx.x * blockDim.x + threadIdx.x;
    int edge = tid >> 5;
    int lane = tid & 31;
    if (edge >= e) return;
    int s = __ldg(&src[edge]);
    int d = __ldg(&dst[edge]);
    float nrm = g_dinv[s] * g_dinv[d];
    float4 v = ((const float4*)(g_h + (size_t)s * CC))[lane];
    v.x *= nrm; v.y *= nrm; v.z *= nrm; v.w *= nrm;
    float* ap = g_agg + (size_t)d * CC + lane * 4;
    asm volatile("red.global.add.v4.f32 [%0], {%1, %2, %3, %4};"
                 :: "l"(ap), "f"(v.x), "f"(v.y), "f"(v.z), "f"(v.w)
                 : "memory");
}

// --------------------- relu*x, LayerNorm, residual, out = y @ W_fc + b_fc ----
// 256 threads = 8 warps, one warp per node. W_fc (128x40) in smem.
__global__ void k_final(const float* __restrict__ x,
                        const float* __restrict__ bconv,
                        const float* __restrict__ gamma,
                        const float* __restrict__ beta,
                        const float* __restrict__ Wfc,
                        const float* __restrict__ bfc,
                        float* __restrict__ out, int n) {
    __shared__ float Wfs[CC * KK];   // 20KB
    __shared__ float bcs[CC], gs[CC], bs[CC], bfs[KK];
    __shared__ float ybuf[8][CC];

    int t = threadIdx.x;
    for (int i = t; i < CC * KK; i += 256) Wfs[i] = Wfc[i];
    if (t < CC) { bcs[t] = bconv[t]; gs[t] = gamma[t]; bs[t] = beta[t]; }
    if (t < KK) bfs[t] = bfc[t];
    __syncthreads();

    int wid = t >> 5;
    int lane = t & 31;
    int node = blockIdx.x * 8 + wid;
    if (node >= n) return;

    float4 a  = ((const float4*)(g_agg + (size_t)node * CC))[lane];
    float4 xv = ((const float4*)(x + (size_t)node * CC))[lane];
    float4 bc = ((const float4*)bcs)[lane];

    a.x = fmaxf(a.x + bc.x, 0.f) * xv.x;
    a.y = fmaxf(a.y + bc.y, 0.f) * xv.y;
    a.z = fmaxf(a.z + bc.z, 0.f) * xv.z;
    a.w = fmaxf(a.w + bc.w, 0.f) * xv.w;

    float s = a.x + a.y + a.z + a.w;
    float q = a.x * a.x + a.y * a.y + a.z * a.z + a.w * a.w;
#pragma unroll
    for (int off = 16; off >= 1; off >>= 1) {
        s += __shfl_xor_sync(0xffffffffu, s, off);
        q += __shfl_xor_sync(0xffffffffu, q, off);
    }
    float mu = s * (1.0f / CC);
    float var = q * (1.0f / CC) - mu * mu;
    float rstd = rsqrtf(var + LN_EPS);

    float4 g = ((const float4*)gs)[lane];
    float4 b = ((const float4*)bs)[lane];
    float4 y;
    y.x = (a.x - mu) * rstd * g.x + b.x + xv.x;
    y.y = (a.y - mu) * rstd * g.y + b.y + xv.y;
    y.z = (a.z - mu) * rstd * g.z + b.z + xv.z;
    y.w = (a.w - mu) * rstd * g.w + b.w + xv.w;
    ((float4*)ybuf[wid])[lane] = y;
    __syncwarp();

    for (int k = lane; k < KK; k += 32) {
        float acc = bfs[k];
#pragma unroll 8
        for (int c = 0; c < CC; c++)
            acc = fmaf(ybuf[wid][c], Wfs[c * KK + k], acc);
        out[(size_t)node * KK + k] = acc;
    }
}

// ---------------------------------------------------------------- launch ----
extern "C" void kernel_launch(void* const* d_in, const int* in_sizes, int n_in,
                              void* d_out, int out_size) {
    const float* x  = (const float*)d_in[0];
    const int*   ei = (const int*)d_in[1];
    const float* Wc = (const float*)d_in[2];
    const float* bc = (const float*)d_in[3];
    const float* gm = (const float*)d_in[4];
    const float* bt = (const float*)d_in[5];
    const float* Wf = (const float*)d_in[6];
    const float* bf = (const float*)d_in[7];
    float* out = (float*)d_out;

    int n = in_sizes[0] / CC;
    int e = in_sizes[1] / 2;
    const int* src = ei;
    const int* dst = ei + e;

    // degree + dinv
    k_deg_init<<<(n + 255) / 256, 256>>>(n);
    k_deg_count<<<(e + 255) / 256, 256>>>(dst, e);
    k_dinv<<<(n + 255) / 256, 256>>>(n);

    // h = x @ W_conv (96KB dynamic smem)
    cudaFuncSetAttribute(k_gemm_h, cudaFuncAttributeMaxDynamicSharedMemorySize, 98304);
    k_gemm_h<<<(n + 63) / 64, 256, 98304>>>(x, Wc, n);

    // agg = self-loop term, then scatter edges
    k_agg_init<<<(n * (CC / 4) + 255) / 256, 256>>>(n);
    {
        long long threads = (long long)e * 32;
        int blocks = (int)((threads + 255) / 256);
        k_scatter<<<blocks, 256>>>(src, dst, e);
    }

    // fused epilogue
    k_final<<<(n + 7) / 8, 256>>>(x, bc, gm, bt, Wf, bf, out, n);
}

// round 4
// speedup vs baseline: 1.2481x; 1.2481x over previous
#include <cuda_runtime.h>
#include <cuda_bf16.h>

#define NN 50000
#define CC 128
#define EE 640000
#define KK 40
#define LN_EPS 1e-5f
#define SCAN_BS 1024
#define MAX_NB 64   // ceil(50000/1024)=49

// Scratch
__device__ int   g_cnt[NN];
__device__ int   g_rowstart[NN + 1];
__device__ int   g_cursor[NN];
__device__ int   g_tmp[NN];
__device__ int   g_bsum[MAX_NB];
__device__ int   g_boff[MAX_NB];
__device__ float g_dinv[NN];
__device__ float g_h[(size_t)NN * CC];
__device__ int   g_csrc[EE];
__device__ float g_cnrm[EE];

// ---------------------------------------------------------------- degree ----
__global__ void k_zero(int n) {
    int i = blockIdx.x * blockDim.x + threadIdx.x;
    if (i < n) g_cnt[i] = 0;
}

__global__ void k_count(const int* __restrict__ dst, int e) {
    int i = blockIdx.x * blockDim.x + threadIdx.x;
    if (i < e) atomicAdd(&g_cnt[dst[i]], 1);
}

// ------------------------------------------------------------------ scan ----
__global__ void k_scan1(int n) {  // grid=NB, block=1024; inclusive scan per block
    __shared__ int sm[SCAN_BS];
    int i = blockIdx.x * SCAN_BS + threadIdx.x;
    int v = (i < n) ? g_cnt[i] : 0;
    sm[threadIdx.x] = v;
    __syncthreads();
#pragma unroll
    for (int off = 1; off < SCAN_BS; off <<= 1) {
        int t = (threadIdx.x >= off) ? sm[threadIdx.x - off] : 0;
        __syncthreads();
        sm[threadIdx.x] += t;
        __syncthreads();
    }
    if (i < n) g_tmp[i] = sm[threadIdx.x];
    if (threadIdx.x == SCAN_BS - 1) g_bsum[blockIdx.x] = sm[SCAN_BS - 1];
}

__global__ void k_scan2(int nb) {  // 1 block, 64 threads
    __shared__ int sm[MAX_NB];
    int v = (threadIdx.x < nb) ? g_bsum[threadIdx.x] : 0;
    sm[threadIdx.x] = v;
    __syncthreads();
#pragma unroll
    for (int off = 1; off < MAX_NB; off <<= 1) {
        int t = (threadIdx.x >= off) ? sm[threadIdx.x - off] : 0;
        __syncthreads();
        sm[threadIdx.x] += t;
        __syncthreads();
    }
    if (threadIdx.x < nb) g_boff[threadIdx.x] = sm[threadIdx.x] - v;  // exclusive
}

__global__ void k_scan3(int n, int e) {
    int i = blockIdx.x * blockDim.x + threadIdx.x;
    if (i < n) {
        int c = g_cnt[i];
        int excl = g_tmp[i] - c + g_boff[i / SCAN_BS];
        g_rowstart[i] = excl;
        g_cursor[i] = excl;
        g_dinv[i] = rsqrtf((float)c + 1.0f);  // +1 self-loop
        if (i == 0) g_rowstart[n] = e;
    }
}

// ------------------------------------------------------------ CSR fill ------
__global__ void k_fill(const int* __restrict__ src, const int* __restrict__ dst, int e) {
    int i = blockIdx.x * blockDim.x + threadIdx.x;
    if (i >= e) return;
    int s = src[i], d = dst[i];
    int pos = atomicAdd(&g_cursor[d], 1);
    g_csrc[pos] = s;
    g_cnrm[pos] = g_dinv[s] * g_dinv[d];
}

// ------------------------------------------------------- h = x @ W_conv ----
__global__ void k_gemm_h(const float* __restrict__ x, const float* __restrict__ W, int n) {
    extern __shared__ float sm[];
    float* Ws = sm;               // 128*128 (64KB)
    float* Xs = sm + CC * CC;     // 64*128 (32KB)
    int t = threadIdx.x;

    float4* Ws4 = (float4*)Ws;
    const float4* W4 = (const float4*)W;
    for (int i = t; i < CC * CC / 4; i += 256) Ws4[i] = W4[i];

    int m0 = blockIdx.x * 64;
    float4* Xs4 = (float4*)Xs;
    for (int i = t; i < 64 * CC / 4; i += 256) {
        int r = i / (CC / 4);
        int cseg = i % (CC / 4);
        float4 v = make_float4(0.f, 0.f, 0.f, 0.f);
        if (m0 + r < n) v = ((const float4*)(x + (size_t)(m0 + r) * CC))[cseg];
        Xs4[i] = v;
    }
    __syncthreads();

    int cg = t & 31;
    int rg = t >> 5;

    float acc[8][4];
#pragma unroll
    for (int r = 0; r < 8; r++)
#pragma unroll
        for (int q = 0; q < 4; q++) acc[r][q] = 0.f;

#pragma unroll 4
    for (int c = 0; c < CC; c++) {
        float4 w = Ws4[c * 32 + cg];
#pragma unroll
        for (int r = 0; r < 8; r++) {
            float xv = Xs[(rg * 8 + r) * CC + c];
            acc[r][0] = fmaf(xv, w.x, acc[r][0]);
            acc[r][1] = fmaf(xv, w.y, acc[r][1]);
            acc[r][2] = fmaf(xv, w.z, acc[r][2]);
            acc[r][3] = fmaf(xv, w.w, acc[r][3]);
        }
    }

#pragma unroll
    for (int r = 0; r < 8; r++) {
        int row = m0 + rg * 8 + r;
        if (row < n)
            ((float4*)(g_h + (size_t)row * CC))[cg] =
                make_float4(acc[r][0], acc[r][1], acc[r][2], acc[r][3]);
    }
}

// ------------- fused: CSR aggregate + relu*x + LN + residual + fc ----------
// One warp per node, 8 warps/block.
__global__ void k_aggfin(const float* __restrict__ x,
                         const float* __restrict__ bconv,
                         const float* __restrict__ gamma,
                         const float* __restrict__ beta,
                         const float* __restrict__ Wfc,
                         const float* __restrict__ bfc,
                         float* __restrict__ out, int n) {
    __shared__ float Wfs[CC * KK];
    __shared__ float bcs[CC], gs[CC], bs[CC], bfs[KK];
    __shared__ float ybuf[8][CC];

    int t = threadIdx.x;
    for (int i = t; i < CC * KK; i += 256) Wfs[i] = Wfc[i];
    if (t < CC) { bcs[t] = bconv[t]; gs[t] = gamma[t]; bs[t] = beta[t]; }
    if (t < KK) bfs[t] = bfc[t];
    __syncthreads();

    int wid = t >> 5;
    int lane = t & 31;
    int node = blockIdx.x * 8 + wid;
    if (node >= n) return;

    int rs = g_rowstart[node];
    int re = g_rowstart[node + 1];
    float dsq = g_dinv[node];
    dsq *= dsq;

    // self-loop seed: dinv^2 * h[node]
    float4 acc = ((const float4*)(g_h + (size_t)node * CC))[lane];
    acc.x *= dsq; acc.y *= dsq; acc.z *= dsq; acc.w *= dsq;

    for (int base = rs; base < re; base += 32) {
        int idx = base + lane;
        int s = 0; float nm = 0.f;
        if (idx < re) { s = g_csrc[idx]; nm = g_cnrm[idx]; }
        int m = min(32, re - base);
        int j = 0;
        for (; j + 4 <= m; j += 4) {
            int s0 = __shfl_sync(0xffffffffu, s, j);
            int s1 = __shfl_sync(0xffffffffu, s, j + 1);
            int s2 = __shfl_sync(0xffffffffu, s, j + 2);
            int s3 = __shfl_sync(0xffffffffu, s, j + 3);
            float n0 = __shfl_sync(0xffffffffu, nm, j);
            float n1 = __shfl_sync(0xffffffffu, nm, j + 1);
            float n2 = __shfl_sync(0xffffffffu, nm, j + 2);
            float n3 = __shfl_sync(0xffffffffu, nm, j + 3);
            float4 v0 = ((const float4*)(g_h + (size_t)s0 * CC))[lane];
            float4 v1 = ((const float4*)(g_h + (size_t)s1 * CC))[lane];
            float4 v2 = ((const float4*)(g_h + (size_t)s2 * CC))[lane];
            float4 v3 = ((const float4*)(g_h + (size_t)s3 * CC))[lane];
            acc.x = fmaf(n0, v0.x, acc.x); acc.y = fmaf(n0, v0.y, acc.y);
            acc.z = fmaf(n0, v0.z, acc.z); acc.w = fmaf(n0, v0.w, acc.w);
            acc.x = fmaf(n1, v1.x, acc.x); acc.y = fmaf(n1, v1.y, acc.y);
            acc.z = fmaf(n1, v1.z, acc.z); acc.w = fmaf(n1, v1.w, acc.w);
            acc.x = fmaf(n2, v2.x, acc.x); acc.y = fmaf(n2, v2.y, acc.y);
            acc.z = fmaf(n2, v2.z, acc.z); acc.w = fmaf(n2, v2.w, acc.w);
            acc.x = fmaf(n3, v3.x, acc.x); acc.y = fmaf(n3, v3.y, acc.y);
            acc.z = fmaf(n3, v3.z, acc.z); acc.w = fmaf(n3, v3.w, acc.w);
        }
        for (; j < m; j++) {
            int sj = __shfl_sync(0xffffffffu, s, j);
            float nj = __shfl_sync(0xffffffffu, nm, j);
            float4 v = ((const float4*)(g_h + (size_t)sj * CC))[lane];
            acc.x = fmaf(nj, v.x, acc.x); acc.y = fmaf(nj, v.y, acc.y);
            acc.z = fmaf(nj, v.z, acc.z); acc.w = fmaf(nj, v.w, acc.w);
        }
    }

    // epilogue: bias, relu, *x, LN, +x, fc
    float4 xv = ((const float4*)(x + (size_t)node * CC))[lane];
    float4 bc = ((const float4*)bcs)[lane];
    acc.x = fmaxf(acc.x + bc.x, 0.f) * xv.x;
    acc.y = fmaxf(acc.y + bc.y, 0.f) * xv.y;
    acc.z = fmaxf(acc.z + bc.z, 0.f) * xv.z;
    acc.w = fmaxf(acc.w + bc.w, 0.f) * xv.w;

    float sU = acc.x + acc.y + acc.z + acc.w;
    float qU = acc.x * acc.x + acc.y * acc.y + acc.z * acc.z + acc.w * acc.w;
#pragma unroll
    for (int off = 16; off >= 1; off >>= 1) {
        sU += __shfl_xor_sync(0xffffffffu, sU, off);
        qU += __shfl_xor_sync(0xffffffffu, qU, off);
    }
    float mu = sU * (1.0f / CC);
    float var = qU * (1.0f / CC) - mu * mu;
    float rstd = rsqrtf(var + LN_EPS);

    float4 g = ((const float4*)gs)[lane];
    float4 b = ((const float4*)bs)[lane];
    float4 y;
    y.x = (acc.x - mu) * rstd * g.x + b.x + xv.x;
    y.y = (acc.y - mu) * rstd * g.y + b.y + xv.y;
    y.z = (acc.z - mu) * rstd * g.z + b.z + xv.z;
    y.w = (acc.w - mu) * rstd * g.w + b.w + xv.w;
    ((float4*)ybuf[wid])[lane] = y;
    __syncwarp();

    for (int k = lane; k < KK; k += 32) {
        float a2 = bfs[k];
#pragma unroll 8
        for (int c = 0; c < CC; c++)
            a2 = fmaf(ybuf[wid][c], Wfs[c * KK + k], a2);
        out[(size_t)node * KK + k] = a2;
    }
}

// ---------------------------------------------------------------- launch ----
extern "C" void kernel_launch(void* const* d_in, const int* in_sizes, int n_in,
                              void* d_out, int out_size) {
    const float* x  = (const float*)d_in[0];
    const int*   ei = (const int*)d_in[1];
    const float* Wc = (const float*)d_in[2];
    const float* bc = (const float*)d_in[3];
    const float* gm = (const float*)d_in[4];
    const float* bt = (const float*)d_in[5];
    const float* Wf = (const float*)d_in[6];
    const float* bf = (const float*)d_in[7];
    float* out = (float*)d_out;

    int n = in_sizes[0] / CC;
    int e = in_sizes[1] / 2;
    const int* src = ei;
    const int* dst = ei + e;
    int nb = (n + SCAN_BS - 1) / SCAN_BS;

    k_zero<<<(n + 255) / 256, 256>>>(n);
    k_count<<<(e + 255) / 256, 256>>>(dst, e);
    k_scan1<<<nb, SCAN_BS>>>(n);
    k_scan2<<<1, MAX_NB>>>(nb);
    k_scan3<<<(n + 255) / 256, 256>>>(n, e);
    k_fill<<<(e + 255) / 256, 256>>>(src, dst, e);

    cudaFuncSetAttribute(k_gemm_h, cudaFuncAttributeMaxDynamicSharedMemorySize, 98304);
    k_gemm_h<<<(n + 63) / 64, 256, 98304>>>(x, Wc, n);

    k_aggfin<<<(n + 7) / 8, 256>>>(x, bc, gm, bt, Wf, bf, out, n);
}

// round 8
// speedup vs baseline: 1.3710x; 1.0985x over previous
#include <cuda_runtime.h>
#include <cuda_bf16.h>
#include <cstdint>

#define NN 50000
#define CC 128
#define EE 640000
#define KK 40
#define LN_EPS 1e-5f
#define SCAN_BS 1024
#define MAX_NB 64

// Scratch
__device__ int   g_cnt[NN];
__device__ int   g_rowstart[NN + 1];
__device__ int   g_cursor[NN];
__device__ int   g_tmp[NN];
__device__ int   g_bsum[MAX_NB];
__device__ int   g_boff[MAX_NB];
__device__ float g_dinv[NN];
__device__ float g_h[(size_t)NN * CC];
__device__ int   g_csrc[EE];
__device__ float g_cnrm[EE];

__device__ __forceinline__ uint32_t f2tf32(float f) {
    uint32_t r;
    asm("cvt.rna.tf32.f32 %0, %1;" : "=r"(r) : "f"(f));
    return r;
}

// ---------------------------------------------------------------- degree ----
__global__ void k_zero(int n) {
    int i = blockIdx.x * blockDim.x + threadIdx.x;
    if (i < n) g_cnt[i] = 0;
}

__global__ void k_count(const int* __restrict__ dst, int e) {
    int i = blockIdx.x * blockDim.x + threadIdx.x;
    if (i < e) atomicAdd(&g_cnt[dst[i]], 1);
}

// ------------------------------------------------------------------ scan ----
__global__ void k_scan1(int n) {
    __shared__ int sm[SCAN_BS];
    int i = blockIdx.x * SCAN_BS + threadIdx.x;
    int v = (i < n) ? g_cnt[i] : 0;
    sm[threadIdx.x] = v;
    __syncthreads();
#pragma unroll
    for (int off = 1; off < SCAN_BS; off <<= 1) {
        int t = (threadIdx.x >= off) ? sm[threadIdx.x - off] : 0;
        __syncthreads();
        sm[threadIdx.x] += t;
        __syncthreads();
    }
    if (i < n) g_tmp[i] = sm[threadIdx.x];
    if (threadIdx.x == SCAN_BS - 1) g_bsum[blockIdx.x] = sm[SCAN_BS - 1];
}

__global__ void k_scan2(int nb) {
    __shared__ int sm[MAX_NB];
    int v = (threadIdx.x < nb) ? g_bsum[threadIdx.x] : 0;
    sm[threadIdx.x] = v;
    __syncthreads();
#pragma unroll
    for (int off = 1; off < MAX_NB; off <<= 1) {
        int t = (threadIdx.x >= off) ? sm[threadIdx.x - off] : 0;
        __syncthreads();
        sm[threadIdx.x] += t;
        __syncthreads();
    }
    if (threadIdx.x < nb) g_boff[threadIdx.x] = sm[threadIdx.x] - v;
}

__global__ void k_scan3(int n, int e) {
    int i = blockIdx.x * blockDim.x + threadIdx.x;
    if (i < n) {
        int c = g_cnt[i];
        int excl = g_tmp[i] - c + g_boff[i / SCAN_BS];
        g_rowstart[i] = excl;
        g_cursor[i] = excl;
        g_dinv[i] = rsqrtf((float)c + 1.0f);
        if (i == 0) g_rowstart[n] = e;
    }
}

// ------------------------------------------------------------ CSR fill ------
__global__ void k_fill(const int* __restrict__ src, const int* __restrict__ dst, int e) {
    int i = blockIdx.x * blockDim.x + threadIdx.x;
    if (i >= e) return;
    int s = src[i], d = dst[i];
    int pos = atomicAdd(&g_cursor[d], 1);
    g_csrc[pos] = s;
    g_cnrm[pos] = g_dinv[s] * g_dinv[d];
}

// --------------------------- h = x @ W_conv via mma.sync tf32 ---------------
// Block: 256 thr (8 warps), tile 128x128. Warp (w&3 -> 32-row band, w>>2 ->
// 64-col band): 2x8 grid of m16n8k8 fragments, K=128 in 16 steps.
// A smem stride 132 floats (bank-free A-frag), B stride 136 (bank-free B-frag).
#define ASTR 132
#define BSTR 136
#define GEMM_SMEM ((128 * ASTR + 128 * BSTR) * 4)

__global__ void __launch_bounds__(256, 1)
k_gemm_mma(const float* __restrict__ x, const float* __restrict__ W, int n) {
    extern __shared__ float sm[];
    float* As = sm;                 // [128][ASTR]
    float* Bs = sm + 128 * ASTR;    // [128][BSTR]
    int t = threadIdx.x;
    int w = t >> 5, lane = t & 31;
    int m0 = blockIdx.x * 128;

    // A: rows of x, converted to tf32
    for (int i = t; i < 128 * 32; i += 256) {
        int r = i >> 5, cs = i & 31;
        float4 v = make_float4(0.f, 0.f, 0.f, 0.f);
        if (m0 + r < n) v = ((const float4*)(x + (size_t)(m0 + r) * CC))[cs];
        float4 tv;
        tv.x = __uint_as_float(f2tf32(v.x));
        tv.y = __uint_as_float(f2tf32(v.y));
        tv.z = __uint_as_float(f2tf32(v.z));
        tv.w = __uint_as_float(f2tf32(v.w));
        *(float4*)(As + r * ASTR + cs * 4) = tv;
    }
    // B: W[k][nc] as-is (k rows)
    for (int i = t; i < 128 * 32; i += 256) {
        int r = i >> 5, cs = i & 31;
        float4 v = ((const float4*)(W + (size_t)r * CC))[cs];
        float4 tv;
        tv.x = __uint_as_float(f2tf32(v.x));
        tv.y = __uint_as_float(f2tf32(v.y));
        tv.z = __uint_as_float(f2tf32(v.z));
        tv.w = __uint_as_float(f2tf32(v.w));
        *(float4*)(Bs + r * BSTR + cs * 4) = tv;
    }
    __syncthreads();

    int wm = (w & 3) * 32;      // warp row base within tile
    int wn = (w >> 2) * 64;     // warp col base
    int grp = lane >> 2;        // 0..7
    int qd  = lane & 3;         // 0..3

    float c[2][8][4];
#pragma unroll
    for (int mi = 0; mi < 2; mi++)
#pragma unroll
        for (int ni = 0; ni < 8; ni++)
#pragma unroll
            for (int q = 0; q < 4; q++) c[mi][ni][q] = 0.f;

#pragma unroll
    for (int k0 = 0; k0 < 128; k0 += 8) {
        uint32_t a[2][4];
#pragma unroll
        for (int mi = 0; mi < 2; mi++) {
            int r0 = wm + mi * 16 + grp;
            a[mi][0] = __float_as_uint(As[r0 * ASTR + k0 + qd]);
            a[mi][1] = __float_as_uint(As[(r0 + 8) * ASTR + k0 + qd]);
            a[mi][2] = __float_as_uint(As[r0 * ASTR + k0 + qd + 4]);
            a[mi][3] = __float_as_uint(As[(r0 + 8) * ASTR + k0 + qd + 4]);
        }
        uint32_t b[8][2];
#pragma unroll
        for (int ni = 0; ni < 8; ni++) {
            int nc = wn + ni * 8 + grp;
            b[ni][0] = __float_as_uint(Bs[(k0 + qd) * BSTR + nc]);
            b[ni][1] = __float_as_uint(Bs[(k0 + qd + 4) * BSTR + nc]);
        }
#pragma unroll
        for (int mi = 0; mi < 2; mi++)
#pragma unroll
            for (int ni = 0; ni < 8; ni++) {
                asm volatile(
                    "mma.sync.aligned.m16n8k8.row.col.f32.tf32.tf32.f32 "
                    "{%0,%1,%2,%3}, {%4,%5,%6,%7}, {%8,%9}, {%0,%1,%2,%3};"
                    : "+f"(c[mi][ni][0]), "+f"(c[mi][ni][1]),
                      "+f"(c[mi][ni][2]), "+f"(c[mi][ni][3])
                    : "r"(a[mi][0]), "r"(a[mi][1]), "r"(a[mi][2]), "r"(a[mi][3]),
                      "r"(b[ni][0]), "r"(b[ni][1]));
            }
    }

    // store: c0,c1 -> (row, col0..col0+1); c2,c3 -> (row+8, same)
#pragma unroll
    for (int mi = 0; mi < 2; mi++) {
        int r0 = m0 + wm + mi * 16 + grp;
#pragma unroll
        for (int ni = 0; ni < 8; ni++) {
            int col = wn + ni * 8 + 2 * qd;
            if (r0 < n)
                *(float2*)(g_h + (size_t)r0 * CC + col) =
                    make_float2(c[mi][ni][0], c[mi][ni][1]);
            if (r0 + 8 < n)
                *(float2*)(g_h + (size_t)(r0 + 8) * CC + col) =
                    make_float2(c[mi][ni][2], c[mi][ni][3]);
        }
    }
}

// ------------- fused: CSR aggregate + relu*x + LN + residual + fc ----------
__global__ void k_aggfin(const float* __restrict__ x,
                         const float* __restrict__ bconv,
                         const float* __restrict__ gamma,
                         const float* __restrict__ beta,
                         const float* __restrict__ Wfc,
                         const float* __restrict__ bfc,
                         float* __restrict__ out, int n) {
    __shared__ float Wfs[CC * KK];
    __shared__ float bcs[CC], gs[CC], bs[CC], bfs[KK];
    __shared__ float ybuf[8][CC];

    int t = threadIdx.x;
    for (int i = t; i < CC * KK; i += 256) Wfs[i] = Wfc[i];
    if (t < CC) { bcs[t] = bconv[t]; gs[t] = gamma[t]; bs[t] = beta[t]; }
    if (t < KK) bfs[t] = bfc[t];
    __syncthreads();

    int wid = t >> 5;
    int lane = t & 31;
    int node = blockIdx.x * 8 + wid;
    if (node >= n) return;

    int rs = g_rowstart[node];
    int re = g_rowstart[node + 1];
    float dsq = g_dinv[node];
    dsq *= dsq;

    float4 acc = ((const float4*)(g_h + (size_t)node * CC))[lane];
    acc.x *= dsq; acc.y *= dsq; acc.z *= dsq; acc.w *= dsq;

    for (int base = rs; base < re; base += 32) {
        int idx = base + lane;
        int s = 0; float nm = 0.f;
        if (idx < re) { s = g_csrc[idx]; nm = g_cnrm[idx]; }
        int m = min(32, re - base);
        int j = 0;
        for (; j + 8 <= m; j += 8) {
            int ss[8]; float nn[8]; float4 vv[8];
#pragma unroll
            for (int q = 0; q < 8; q++) {
                ss[q] = __shfl_sync(0xffffffffu, s, j + q);
                nn[q] = __shfl_sync(0xffffffffu, nm, j + q);
            }
#pragma unroll
            for (int q = 0; q < 8; q++)
                vv[q] = ((const float4*)(g_h + (size_t)ss[q] * CC))[lane];
#pragma unroll
            for (int q = 0; q < 8; q++) {
                acc.x = fmaf(nn[q], vv[q].x, acc.x);
                acc.y = fmaf(nn[q], vv[q].y, acc.y);
                acc.z = fmaf(nn[q], vv[q].z, acc.z);
                acc.w = fmaf(nn[q], vv[q].w, acc.w);
            }
        }
        for (; j + 4 <= m; j += 4) {
            int ss[4]; float nn[4]; float4 vv[4];
#pragma unroll
            for (int q = 0; q < 4; q++) {
                ss[q] = __shfl_sync(0xffffffffu, s, j + q);
                nn[q] = __shfl_sync(0xffffffffu, nm, j + q);
            }
#pragma unroll
            for (int q = 0; q < 4; q++)
                vv[q] = ((const float4*)(g_h + (size_t)ss[q] * CC))[lane];
#pragma unroll
            for (int q = 0; q < 4; q++) {
                acc.x = fmaf(nn[q], vv[q].x, acc.x);
                acc.y = fmaf(nn[q], vv[q].y, acc.y);
                acc.z = fmaf(nn[q], vv[q].z, acc.z);
                acc.w = fmaf(nn[q], vv[q].w, acc.w);
            }
        }
        for (; j < m; j++) {
            int sj = __shfl_sync(0xffffffffu, s, j);
            float nj = __shfl_sync(0xffffffffu, nm, j);
            float4 v = ((const float4*)(g_h + (size_t)sj * CC))[lane];
            acc.x = fmaf(nj, v.x, acc.x); acc.y = fmaf(nj, v.y, acc.y);
            acc.z = fmaf(nj, v.z, acc.z); acc.w = fmaf(nj, v.w, acc.w);
        }
    }

    float4 xv = ((const float4*)(x + (size_t)node * CC))[lane];
    float4 bc = ((const float4*)bcs)[lane];
    acc.x = fmaxf(acc.x + bc.x, 0.f) * xv.x;
    acc.y = fmaxf(acc.y + bc.y, 0.f) * xv.y;
    acc.z = fmaxf(acc.z + bc.z, 0.f) * xv.z;
    acc.w = fmaxf(acc.w + bc.w, 0.f) * xv.w;

    float sU = acc.x + acc.y + acc.z + acc.w;
    float qU = acc.x * acc.x + acc.y * acc.y + acc.z * acc.z + acc.w * acc.w;
#pragma unroll
    for (int off = 16; off >= 1; off >>= 1) {
        sU += __shfl_xor_sync(0xffffffffu, sU, off);
        qU += __shfl_xor_sync(0xffffffffu, qU, off);
    }
    float mu = sU * (1.0f / CC);
    float var = qU * (1.0f / CC) - mu * mu;
    float rstd = rsqrtf(var + LN_EPS);

    float4 g = ((const float4*)gs)[lane];
    float4 b = ((const float4*)bs)[lane];
    float4 y;
    y.x = (acc.x - mu) * rstd * g.x + b.x + xv.x;
    y.y = (acc.y - mu) * rstd * g.y + b.y + xv.y;
    y.z = (acc.z - mu) * rstd * g.z + b.z + xv.z;
    y.w = (acc.w - mu) * rstd * g.w + b.w + xv.w;
    ((float4*)ybuf[wid])[lane] = y;
    __syncwarp();

    for (int k = lane; k < KK; k += 32) {
        float a2 = bfs[k];
#pragma unroll 8
        for (int c = 0; c < CC; c++)
            a2 = fmaf(ybuf[wid][c], Wfs[c * KK + k], a2);
        out[(size_t)node * KK + k] = a2;
    }
}

// ---------------------------------------------------------------- launch ----
extern "C" void kernel_launch(void* const* d_in, const int* in_sizes, int n_in,
                              void* d_out, int out_size) {
    const float* x  = (const float*)d_in[0];
    const int*   ei = (const int*)d_in[1];
    const float* Wc = (const float*)d_in[2];
    const float* bc = (const float*)d_in[3];
    const float* gm = (const float*)d_in[4];
    const float* bt = (const float*)d_in[5];
    const float* Wf = (const float*)d_in[6];
    const float* bf = (const float*)d_in[7];
    float* out = (float*)d_out;

    int n = in_sizes[0] / CC;
    int e = in_sizes[1] / 2;
    const int* src = ei;
    const int* dst = ei + e;
    int nb = (n + SCAN_BS - 1) / SCAN_BS;

    k_zero<<<(n + 255) / 256, 256>>>(n);
    k_count<<<(e + 255) / 256, 256>>>(dst, e);
    k_scan1<<<nb, SCAN_BS>>>(n);
    k_scan2<<<1, MAX_NB>>>(nb);
    k_scan3<<<(n + 255) / 256, 256>>>(n, e);
    k_fill<<<(e + 255) / 256, 256>>>(src, dst, e);

    cudaFuncSetAttribute(k_gemm_mma, cudaFuncAttributeMaxDynamicSharedMemorySize, GEMM_SMEM);
    k_gemm_mma<<<(n + 127) / 128, 256, GEMM_SMEM>>>(x, Wc, n);

    k_aggfin<<<(n + 7) / 8, 256>>>(x, bc, gm, bt, Wf, bf, out, n);
}